// round 11
// baseline (speedup 1.0000x reference)
#include <cuda_runtime.h>
#include <cuda_fp16.h>
#include <cstdint>

#define BB 4
#define CC 64
#define FD 50000
#define KN 16
#define BN_EPS 1e-5f

#define GEMM_TILES 391     // (FD+127)/128
#define GATHER_TILES 1563  // (FD+31)/32
#define GEMM_CTAS (BB * GEMM_TILES)
#define GATHER_CTAS (BB * GATHER_TILES)

// Scratch: transformed features g[b][f][o] in fp16 (face-major, 128B rows)
__device__ __half g_buf[BB * FD * CC];
__device__ float g_sum[CC];
__device__ float g_sq[CC];
__device__ int g_done[BB];   // reset to 0 by norm_kernel each call

// ---------------------------------------------------------------------------
__device__ __forceinline__ uint32_t smem_u32(const void* p) {
    uint32_t a;
    asm("{ .reg .u64 t; cvta.to.shared.u64 t, %1; cvt.u32.u64 %0, t; }"
        : "=r"(a) : "l"(p));
    return a;
}

__device__ __forceinline__ int ld_acquire_gpu(const int* p) {
    int v;
    asm volatile("ld.acquire.gpu.b32 %0, [%1];" : "=r"(v) : "l"(p) : "memory");
    return v;
}

__device__ __forceinline__ void ldsm_x4(uint32_t& r0, uint32_t& r1,
                                        uint32_t& r2, uint32_t& r3, uint32_t addr) {
    asm volatile("ldmatrix.sync.aligned.m8n8.x4.shared.b16 {%0,%1,%2,%3}, [%4];"
                 : "=r"(r0), "=r"(r1), "=r"(r2), "=r"(r3) : "r"(addr));
}

__device__ __forceinline__ void ldsm_x4_trans(uint32_t& r0, uint32_t& r1,
                                              uint32_t& r2, uint32_t& r3, uint32_t addr) {
    asm volatile("ldmatrix.sync.aligned.m8n8.x4.trans.shared.b16 {%0,%1,%2,%3}, [%4];"
                 : "=r"(r0), "=r"(r1), "=r"(r2), "=r"(r3) : "r"(addr));
}

__device__ __forceinline__ void mma16816(float* c, uint32_t a0, uint32_t a1,
                                         uint32_t a2, uint32_t a3,
                                         uint32_t b0, uint32_t b1) {
    asm volatile(
        "mma.sync.aligned.m16n8k16.row.col.f32.f16.f16.f32 "
        "{%0,%1,%2,%3}, {%4,%5,%6,%7}, {%8,%9}, {%0,%1,%2,%3};"
        : "+f"(c[0]), "+f"(c[1]), "+f"(c[2]), "+f"(c[3])
        : "r"(a0), "r"(a1), "r"(a2), "r"(a3), "r"(b0), "r"(b1));
}

// ---------------------------------------------------------------------------
// Fused gemm + gather. Grid = [GEMM_CTAS][GATHER_CTAS], 256 threads.
// gemm CTAs come FIRST in dispatch order (deadlock safety for the spin).
// gemm(b) completion is signaled via g_done[b]; gather(b) CTAs spin-wait.
#define SPA 136  // sA row stride in halves (272B == 16 mod 128)
#define SPB 72   // sB row stride in halves (144B == 16 mod 128)

struct SmemGemm {
    __align__(16) __half A[64 * SPA];   // [c][f]
    __align__(16) __half B[64 * SPB];   // [o][c]
};
struct SmemGather {
    float tile[32][65];
    float ssum[CC];
    float ssq[CC];
};
union SmemU {
    SmemGemm g;
    SmemGather h;
};

__global__ __launch_bounds__(256)
void fused_kernel(const float* __restrict__ fea, const float* __restrict__ W,
                  const int* __restrict__ ring, const float* __restrict__ bias,
                  float* __restrict__ out) {
    __shared__ SmemU sm;
    const int bid = blockIdx.x;
    const int t = threadIdx.x;
    const int wid = t >> 5, lane = t & 31;

    if (bid < GEMM_CTAS) {
        // =================== GEMM part ===================
        const int b = bid / GEMM_TILES;
        const int tile = bid % GEMM_TILES;
        const int f0 = tile * 128;
        __half* sA = sm.g.A;
        __half* sB = sm.g.B;

        // per-batch tile-0 CTA zeroes stats (redundant same-value writes OK;
        // visibility to gather(b) flows through the g_done[b] chain)
        if (tile == 0 && t < CC) { g_sum[t] = 0.f; g_sq[t] = 0.f; }

        // ---- stage B = W [64o][64c] -> fp16 padded rows ----
        {
            const int o = t >> 2, q = t & 3;
            union { __half2 h2[8]; uint4 u[2]; } pk;
#pragma unroll
            for (int i = 0; i < 4; i++) {
                float4 wv = *(const float4*)(W + o * CC + q * 16 + 4 * i);
                pk.h2[2 * i]     = __floats2half2_rn(wv.x, wv.y);
                pk.h2[2 * i + 1] = __floats2half2_rn(wv.z, wv.w);
            }
            uint4* dst = (uint4*)(sB + o * SPB + q * 16);
            dst[0] = pk.u[0];
            dst[1] = pk.u[1];
        }

        // ---- stage A = fea tile [64c][128f] fp16 as-is ----
        const float* feab = fea + (size_t)b * (CC * FD);
        const int nv = min(128, FD - f0);
        {
            const int c = t >> 2, q = t & 3;
            const float* src = feab + c * FD + f0 + q * 32;
            __half* dstrow = sA + c * SPA + q * 32;
#pragma unroll
            for (int i = 0; i < 8; i++) {
                float4 v = make_float4(0.f, 0.f, 0.f, 0.f);
                if (q * 32 + 4 * i + 3 < nv) v = *(const float4*)(src + 4 * i);
                union { __half2 h2[2]; unsigned long long u; } pk;
                pk.h2[0] = __floats2half2_rn(v.x, v.y);
                pk.h2[1] = __floats2half2_rn(v.z, v.w);
                *(unsigned long long*)(dstrow + 4 * i) = pk.u;
            }
        }
        __syncthreads();

        // ---- MMA mainloop ----
        const uint32_t aBase = smem_u32(sA);
        const uint32_t bBase = smem_u32(sB);
        const int m0 = wid * 16;
        const int g = lane >> 3, r = lane & 7;
        const uint32_t aKoff = (g >> 1) * 8 + r;
        const uint32_t aMcol = m0 + (g & 1) * 8;
        const uint32_t bRowOff = (lane >> 4) * 8 + (lane & 7);
        const uint32_t bColOff = ((lane >> 3) & 1) * 8;

        float acc[8][4];
#pragma unroll
        for (int j = 0; j < 8; j++)
#pragma unroll
            for (int m = 0; m < 4; m++) acc[j][m] = 0.f;

#pragma unroll
        for (int kk = 0; kk < 4; kk++) {
            uint32_t a0, a1, a2, a3;
            ldsm_x4_trans(a0, a1, a2, a3,
                          aBase + ((kk * 16 + aKoff) * SPA + aMcol) * 2);
#pragma unroll
            for (int j = 0; j < 4; j++) {
                uint32_t b0, b1, b2, b3;
                ldsm_x4(b0, b1, b2, b3,
                        bBase + ((16 * j + bRowOff) * SPB + kk * 16 + bColOff) * 2);
                mma16816(acc[2 * j],     a0, a1, a2, a3, b0, b1);
                mma16816(acc[2 * j + 1], a0, a1, a2, a3, b2, b3);
            }
        }

        // ---- epilogue -> g_buf[f][o] fp16 ----
        const int fr = f0 + m0 + (lane >> 2);
        const int colq = 2 * (lane & 3);
        __half* gb = g_buf + (size_t)b * (FD * CC);
        if (fr < FD) {
            __half* row = gb + (size_t)fr * CC;
#pragma unroll
            for (int j = 0; j < 8; j++)
                *(__half2*)(row + 8 * j + colq) = __floats2half2_rn(acc[j][0], acc[j][1]);
        }
        if (fr + 8 < FD) {
            __half* row = gb + (size_t)(fr + 8) * CC;
#pragma unroll
            for (int j = 0; j < 8; j++)
                *(__half2*)(row + 8 * j + colq) = __floats2half2_rn(acc[j][2], acc[j][3]);
        }

        // ---- signal completion of this gemm tile ----
        __syncthreads();
        __threadfence();
        if (t == 0) atomicAdd(&g_done[b], 1);

    } else {
        // =================== GATHER part ===================
        const int gid = bid - GEMM_CTAS;
        const int b = gid / GATHER_TILES;
        const int f0 = (gid % GATHER_TILES) * 32;
        const int warp = wid;

        // prefetch ring indices (independent of gemm) before the spin
        int myidx[4];
#pragma unroll
        for (int i = 0; i < 4; i++) {
            int f = f0 + warp * 4 + i;
            myidx[i] = 0;
            if (f < FD && lane < KN) {
                int v = ring[((long long)(b * FD + f)) * KN + lane];
                if ((unsigned)v < (unsigned)FD) myidx[i] = v;  // defensive
            }
        }

        if (t < CC) { sm.h.ssum[t] = 0.f; sm.h.ssq[t] = 0.f; }

        // wait for gemm(b) to finish (acquire)
        if (t == 0) {
            while (ld_acquire_gpu(&g_done[b]) < GEMM_TILES) __nanosleep(200);
        }
        __syncthreads();

        const __half2* gb = (const __half2*)(g_buf + (size_t)b * (FD * CC));
        const float bias0 = bias[2 * lane];
        const float bias1 = bias[2 * lane + 1];

        float s0 = 0.f, s1 = 0.f, q0 = 0.f, q1 = 0.f;

#pragma unroll
        for (int i = 0; i < 4; i++) {
            int f = f0 + warp * 4 + i;
            if (f >= FD) continue;
            float accx = 0.f, accy = 0.f;
#pragma unroll
            for (int k = 0; k < KN; k++) {
                int idx = __shfl_sync(0xffffffffu, myidx[i], k);
                float2 v = __half22float2(gb[(size_t)idx * 32 + lane]);
                accx += v.x;
                accy += v.y;
            }
            float y0 = accx + bias0;
            float y1 = accy + bias1;
            sm.h.tile[warp * 4 + i][2 * lane]     = y0;
            sm.h.tile[warp * 4 + i][2 * lane + 1] = y1;
            s0 += y0; q0 += y0 * y0;
            s1 += y1; q1 += y1 * y1;
        }

        atomicAdd(&sm.h.ssum[2 * lane],     s0);
        atomicAdd(&sm.h.ssum[2 * lane + 1], s1);
        atomicAdd(&sm.h.ssq[2 * lane],      q0);
        atomicAdd(&sm.h.ssq[2 * lane + 1],  q1);
        __syncthreads();

        // transposed, coalesced write: out[b][c][f0+lane]
        const int nf = min(32, FD - f0);
        for (int c = warp; c < CC; c += 8) {
            if (lane < nf)
                out[((size_t)b * CC + c) * FD + f0 + lane] = sm.h.tile[lane][c];
        }

        if (t < CC) {
            atomicAdd(&g_sum[t], sm.h.ssum[t]);
            atomicAdd(&g_sq[t],  sm.h.ssq[t]);
        }
    }
}

// ---------------------------------------------------------------------------
// In-place normalize + ReLU over d_out, float4 vectorized, BN finalize inline.
// Also resets g_done for the next call (stream-ordered; nothing in this
// kernel reads g_done).
__global__ __launch_bounds__(256) void norm_kernel(const float* __restrict__ gamma,
                                                   const float* __restrict__ beta,
                                                   float* __restrict__ out) {
    if (blockIdx.x == 0 && threadIdx.x < BB) g_done[threadIdx.x] = 0;
    int i = blockIdx.x * 256 + threadIdx.x;       // float4 index
    int c = (i / (FD / 4)) & 63;                  // channel
    const float inv_n = 1.0f / (float)(BB * FD);
    float mean = g_sum[c] * inv_n;
    float var  = g_sq[c] * inv_n - mean * mean;
    float sc = gamma[c] * rsqrtf(var + BN_EPS);
    float sh = beta[c] - mean * sc;
    float4 v = ((float4*)out)[i];
    v.x = fmaxf(fmaf(v.x, sc, sh), 0.f);
    v.y = fmaxf(fmaf(v.y, sc, sh), 0.f);
    v.z = fmaxf(fmaf(v.z, sc, sh), 0.f);
    v.w = fmaxf(fmaf(v.w, sc, sh), 0.f);
    ((float4*)out)[i] = v;
}

// ---------------------------------------------------------------------------
extern "C" void kernel_launch(void* const* d_in, const int* in_sizes, int n_in,
                              void* d_out, int out_size) {
    const float* fea   = (const float*)d_in[0];      // [B, C_in, F]
    const int*   ring  = (const int*)d_in[1];        // [B, F, K] int32
    const float* W     = (const float*)d_in[2];      // [C_out, C_in]
    const float* bias  = (const float*)d_in[3];      // [C_out]
    const float* gamma = (const float*)d_in[4];      // [C_out]
    const float* beta  = (const float*)d_in[5];      // [C_out]
    float*       out   = (float*)d_out;              // [B, C_out, F]

    fused_kernel<<<GEMM_CTAS + GATHER_CTAS, 256>>>(fea, W, ring, bias, out);

    norm_kernel<<<(BB * CC * FD / 4) / 256, 256>>>(gamma, beta, out);
}